// round 10
// baseline (speedup 1.0000x reference)
#include <cuda_runtime.h>
#include <cuda_fp16.h>
#include <math.h>

#define N_NODES 100000
#define N_EDGES 3200000
#define N_GRAPHS 128
#define SCAN_CHUNKS 98            // ceil(100000/1024)

// ---------------- device scratch ----------------
__device__ int   g_is64;
__device__ int   g_cnt[N_NODES];
__device__ float g_dinv[N_NODES];
__device__ int   g_rowptr[N_NODES + 1];
__device__ int2  g_tmp[N_EDGES];            // (src, d<<15 | pos_within_row)
__device__ int2  g_edge[N_EDGES];           // (src, bitcast weight)
__device__ float g_agg[N_NODES * 64];       // fp32 aggregation output
__device__ __half2 g_h16[N_NODES * 32];     // fp16 hidden features [N,64]
__device__ __half2 g_x16[N_NODES * 16];     // fp16 padded input    [N,32]
__device__ float g_psum[N_GRAPHS * 64];
__device__ int   g_start[N_GRAPHS + 1];
__device__ int   g_bsum[128];
__device__ int   g_boff[128];

// ---------------- helpers ----------------
__device__ __forceinline__ int ld_idx(const void* p, long long i) {
    if (g_is64) return (int)((const long long*)p)[i];
    return ((const int*)p)[i];
}

// ---------------- dtype probe ----------------
__global__ void k_detect(const void* p) {
    if (threadIdx.x != 0 || blockIdx.x != 0) return;
    const long long* q = (const long long*)p;
    int ok64 = 1;
    for (int i = 0; i < 256; i++) {
        long long v = q[i];
        if (v < 0 || v >= (long long)N_NODES) { ok64 = 0; break; }
    }
    g_is64 = ok64;
}

// ---------------- prep: zero counters + convert x to padded fp16 [N,32] -------
__global__ void k_prep(const float* __restrict__ x) {
    int i = blockIdx.x * blockDim.x + threadIdx.x;
    if (i < N_NODES) g_cnt[i] = 0;
    if (i < N_GRAPHS * 64) g_psum[i] = 0.f;
    if (i < N_NODES * 16) {
        int n = i >> 4, j = i & 15;
        int f = 2 * j;
        float a = (f < 20) ? x[n * 20 + f] : 0.f;
        float b = (f + 1 < 20) ? x[n * 20 + f + 1] : 0.f;
        g_x16[i] = __floats2half2_rn(a, b);
    }
}

// ---------------- graph boundaries (batch sorted, no atomics) ----------------
__global__ void k_bound(const void* p) {
    int i = blockIdx.x * blockDim.x + threadIdx.x;
    if (i >= N_NODES) return;
    int b = ld_idx(p, i);
    int prev = (i == 0) ? -1 : ld_idx(p, i - 1);
    for (int g = prev + 1; g <= b; g++) g_start[g] = i;
    if (i == N_NODES - 1)
        for (int g = b + 1; g <= N_GRAPHS; g++) g_start[g] = N_NODES;
}

// ---------------- Pass A: single atomic pass — count + provisional place ------
// 2 edges/thread, 16B index loads. pos_within_row fits 15 bits (max in-degree
// of Binomial(3.2M, 1e-5) is ~90), d fits 17 bits.
__global__ void k_passA(const void* p) {
    int t = blockIdx.x * blockDim.x + threadIdx.x;
    if (t >= N_EDGES / 2) return;
    int s0, s1, d0, d1;
    if (g_is64) {
        const longlong2* qs = (const longlong2*)p;
        const longlong2* qd = (const longlong2*)((const long long*)p + N_EDGES);
        longlong2 sv = __ldg(&qs[t]);
        longlong2 dv = __ldg(&qd[t]);
        s0 = (int)sv.x; s1 = (int)sv.y;
        d0 = (int)dv.x; d1 = (int)dv.y;
    } else {
        const int2* qs = (const int2*)p;
        const int2* qd = (const int2*)((const int*)p + N_EDGES);
        int2 sv = __ldg(&qs[t]);
        int2 dv = __ldg(&qd[t]);
        s0 = sv.x; s1 = sv.y;
        d0 = dv.x; d1 = dv.y;
    }
    int p0 = atomicAdd(&g_cnt[d0], 1);
    int p1 = atomicAdd(&g_cnt[d1], 1);
    g_tmp[2 * t]     = make_int2(s0, (int)(((unsigned)d0 << 15) | (unsigned)p0));
    g_tmp[2 * t + 1] = make_int2(s1, (int)(((unsigned)d1 << 15) | (unsigned)p1));
}

// ---------------- multi-block scan ----------------
__global__ __launch_bounds__(1024) void k_scan1() {
    int tid = threadIdx.x;
    int lane = tid & 31, wid = tid >> 5;
    int i = blockIdx.x * 1024 + tid;
    int v = (i < N_NODES) ? g_cnt[i] : 0;
    int x = v;
    #pragma unroll
    for (int off = 1; off < 32; off <<= 1) {
        int t = __shfl_up_sync(0xFFFFFFFFu, x, off);
        if (lane >= off) x += t;
    }
    __shared__ int ws[32];
    if (lane == 31) ws[wid] = x;
    __syncthreads();
    if (wid == 0) {
        int y = ws[lane];
        #pragma unroll
        for (int off = 1; off < 32; off <<= 1) {
            int t = __shfl_up_sync(0xFFFFFFFFu, y, off);
            if (lane >= off) y += t;
        }
        ws[lane] = y;
    }
    __syncthreads();
    int incl = x + (wid > 0 ? ws[wid - 1] : 0);
    if (i < N_NODES) g_rowptr[i] = incl - v;
    if (tid == 1023) g_bsum[blockIdx.x] = incl;
}

__global__ void k_scan2() {
    __shared__ int sh[128];
    int t = threadIdx.x;
    int v = (t < SCAN_CHUNKS) ? g_bsum[t] : 0;
    sh[t] = v;
    __syncthreads();
    #pragma unroll
    for (int off = 1; off < 128; off <<= 1) {
        int u = (t >= off) ? sh[t - off] : 0;
        __syncthreads();
        sh[t] += u;
        __syncthreads();
    }
    if (t < SCAN_CHUNKS) g_boff[t] = sh[t] - v;
    if (t == 127) g_rowptr[N_NODES] = sh[127];
}

__global__ void k_scan3() {
    int i = blockIdx.x * blockDim.x + threadIdx.x;
    if (i >= N_NODES) return;
    g_rowptr[i] += g_boff[i >> 10];
    g_dinv[i] = rsqrtf((float)g_cnt[i] + 1.0f);
}

// ---------------- Pass B: sequential temp read -> final scatter (no atomics) ---
__global__ void k_passB() {
    int t = blockIdx.x * blockDim.x + threadIdx.x;
    if (t >= N_EDGES / 2) return;
    int4 rec = __ldg((const int4*)&g_tmp[2 * t]);
    {
        int s = rec.x;
        unsigned pk = (unsigned)rec.y;
        int d = (int)(pk >> 15);
        int pos = g_rowptr[d] + (int)(pk & 0x7FFFu);
        g_edge[pos] = make_int2(s, __float_as_int(g_dinv[s] * g_dinv[d]));
    }
    {
        int s = rec.z;
        unsigned pk = (unsigned)rec.w;
        int d = (int)(pk >> 15);
        int pos = g_rowptr[d] + (int)(pk & 0x7FFFu);
        g_edge[pos] = make_int2(s, __float_as_int(g_dinv[s] * g_dinv[d]));
    }
}

// ---------------- aggregation F=20: 2 lane-groups x 2-deep unroll --------------
__global__ __launch_bounds__(256) void k_agg20(const float* __restrict__ x) {
    int i = (blockIdx.x * blockDim.x + threadIdx.x) >> 5;
    int lane = threadIdx.x & 31;
    int grp = lane >> 4;
    int lj = lane & 15;
    int beg = g_rowptr[i], end = g_rowptr[i + 1];
    float ax = 0.f, ay = 0.f;
    int e = beg + grp;
    for (; e + 2 < end; e += 4) {
        int2 e0 = g_edge[e];
        int2 e1 = g_edge[e + 2];
        float2 v0 = __half22float2(__ldg(&g_x16[e0.x * 16 + lj]));
        float2 v1 = __half22float2(__ldg(&g_x16[e1.x * 16 + lj]));
        float w0 = __int_as_float(e0.y), w1 = __int_as_float(e1.y);
        ax = fmaf(w0, v0.x, ax); ay = fmaf(w0, v0.y, ay);
        ax = fmaf(w1, v1.x, ax); ay = fmaf(w1, v1.y, ay);
    }
    if (e < end) {
        int2 e0 = g_edge[e];
        float2 v = __half22float2(__ldg(&g_x16[e0.x * 16 + lj]));
        float w = __int_as_float(e0.y);
        ax = fmaf(w, v.x, ax); ay = fmaf(w, v.y, ay);
    }
    ax += __shfl_xor_sync(0xFFFFFFFFu, ax, 16);
    ay += __shfl_xor_sync(0xFFFFFFFFu, ay, 16);
    if (lane < 10) {
        float di = g_dinv[i];
        float dd = di * di;
        int f = 2 * lane;
        float2 o;
        o.x = fmaf(dd, x[i * 20 + f], ax);
        o.y = fmaf(dd, x[i * 20 + f + 1], ay);
        *(float2*)&g_agg[i * 20 + f] = o;
    }
}

// ---------------- aggregation F=64, warp per node, 4-edge unroll ----------------
template <bool POOL>
__device__ __forceinline__ void agg64_body(const void* batch) {
    __shared__ float sacc[64];
    __shared__ int sg;
    int i = (blockIdx.x * blockDim.x + threadIdx.x) >> 5;   // grid exact: no tail
    int lane = threadIdx.x & 31;
    if (POOL) {
        if (threadIdx.x < 64) sacc[threadIdx.x] = 0.f;
        if (threadIdx.x == 0) sg = ld_idx(batch, (blockIdx.x * blockDim.x) >> 5);
        __syncthreads();
    }
    int beg = g_rowptr[i], end = g_rowptr[i + 1];
    float ax = 0.f, ay = 0.f;
    int e = beg;
    for (; e + 4 <= end; e += 4) {
        int2 e0 = g_edge[e];
        int2 e1 = g_edge[e + 1];
        int2 e2 = g_edge[e + 2];
        int2 e3 = g_edge[e + 3];
        float2 v0 = __half22float2(__ldg(&g_h16[e0.x * 32 + lane]));
        float2 v1 = __half22float2(__ldg(&g_h16[e1.x * 32 + lane]));
        float2 v2 = __half22float2(__ldg(&g_h16[e2.x * 32 + lane]));
        float2 v3 = __half22float2(__ldg(&g_h16[e3.x * 32 + lane]));
        float w0 = __int_as_float(e0.y), w1 = __int_as_float(e1.y);
        float w2 = __int_as_float(e2.y), w3 = __int_as_float(e3.y);
        ax = fmaf(w0, v0.x, ax); ay = fmaf(w0, v0.y, ay);
        ax = fmaf(w1, v1.x, ax); ay = fmaf(w1, v1.y, ay);
        ax = fmaf(w2, v2.x, ax); ay = fmaf(w2, v2.y, ay);
        ax = fmaf(w3, v3.x, ax); ay = fmaf(w3, v3.y, ay);
    }
    for (; e < end; e++) {
        int2 e0 = g_edge[e];
        float2 v = __half22float2(__ldg(&g_h16[e0.x * 32 + lane]));
        float w = __int_as_float(e0.y);
        ax = fmaf(w, v.x, ax); ay = fmaf(w, v.y, ay);
    }
    float di = g_dinv[i];
    float dd = di * di;
    float2 xv = __half22float2(g_h16[i * 32 + lane]);
    ax = fmaf(dd, xv.x, ax); ay = fmaf(dd, xv.y, ay);
    if (!POOL) {
        float2 o; o.x = ax; o.y = ay;
        ((float2*)g_agg)[i * 32 + lane] = o;
    } else {
        int b = ld_idx(batch, i);
        int uniform = __syncthreads_and(b == sg);
        if (uniform) {
            atomicAdd(&sacc[2 * lane], ax);
            atomicAdd(&sacc[2 * lane + 1], ay);
            __syncthreads();
            if (threadIdx.x < 64)
                atomicAdd(&g_psum[sg * 64 + threadIdx.x], sacc[threadIdx.x]);
        } else {
            atomicAdd(&g_psum[b * 64 + 2 * lane], ax);
            atomicAdd(&g_psum[b * 64 + 2 * lane + 1], ay);
        }
    }
}

__global__ __launch_bounds__(256) void k_agg64() { agg64_body<false>(nullptr); }
__global__ __launch_bounds__(256) void k_agg64_pool(const void* batch) {
    agg64_body<true>(batch);
}

// ---------------- FMA-bound matmul: 64-node tile, 4x4 outer product -----------
template <int FIN>
__device__ __forceinline__ void mm_body_h(const float* __restrict__ in,
                                          const float* __restrict__ W,
                                          const float* __restrict__ b) {
    constexpr int FOUT = 64;
    constexpr int NT = 64;
    __shared__ float Ws[FIN * FOUT];
    __shared__ float bs[FOUT];
    __shared__ float rT[FIN][NT + 4];
    for (int k = threadIdx.x; k < FIN * FOUT; k += 256) Ws[k] = W[k];
    if (threadIdx.x < FOUT) bs[threadIdx.x] = b[threadIdx.x];
    int cg = threadIdx.x & 15;
    int ng = threadIdx.x >> 4;
    int c0 = cg * 4, nb = ng * 4;
    const int ntiles = (N_NODES + NT - 1) / NT;
    for (int tile = blockIdx.x; tile < ntiles; tile += gridDim.x) {
        int n0 = tile * NT;
        for (int idx = threadIdx.x; idx < NT * FIN; idx += 256) {
            int n = idx / FIN, k = idx - n * FIN;
            int node = n0 + n;
            rT[k][n] = (node < N_NODES) ? in[node * FIN + k] : 0.f;
        }
        __syncthreads();
        float a0x = bs[c0], a0y = bs[c0+1], a0z = bs[c0+2], a0w = bs[c0+3];
        float a1x = a0x, a1y = a0y, a1z = a0z, a1w = a0w;
        float a2x = a0x, a2y = a0y, a2z = a0z, a2w = a0w;
        float a3x = a0x, a3y = a0y, a3z = a0z, a3w = a0w;
        #pragma unroll 4
        for (int k = 0; k < FIN; k++) {
            float4 rv = *(const float4*)&rT[k][nb];
            float4 wv = *(const float4*)&Ws[k * FOUT + c0];
            a0x = fmaf(rv.x, wv.x, a0x); a0y = fmaf(rv.x, wv.y, a0y);
            a0z = fmaf(rv.x, wv.z, a0z); a0w = fmaf(rv.x, wv.w, a0w);
            a1x = fmaf(rv.y, wv.x, a1x); a1y = fmaf(rv.y, wv.y, a1y);
            a1z = fmaf(rv.y, wv.z, a1z); a1w = fmaf(rv.y, wv.w, a1w);
            a2x = fmaf(rv.z, wv.x, a2x); a2y = fmaf(rv.z, wv.y, a2y);
            a2z = fmaf(rv.z, wv.z, a2z); a2w = fmaf(rv.z, wv.w, a2w);
            a3x = fmaf(rv.w, wv.x, a3x); a3y = fmaf(rv.w, wv.y, a3y);
            a3z = fmaf(rv.w, wv.z, a3z); a3w = fmaf(rv.w, wv.w, a3w);
        }
        #define MM_STORE_H(NI, AX, AY, AZ, AW)                                \
        {                                                                     \
            int node = n0 + nb + NI;                                          \
            if (node < N_NODES) {                                             \
                __half2 h01 = __floats2half2_rn(fmaxf(AX, 0.f), fmaxf(AY, 0.f)); \
                __half2 h23 = __floats2half2_rn(fmaxf(AZ, 0.f), fmaxf(AW, 0.f)); \
                uint2 u;                                                      \
                u.x = *reinterpret_cast<unsigned*>(&h01);                     \
                u.y = *reinterpret_cast<unsigned*>(&h23);                     \
                *(uint2*)&g_h16[node * 32 + (c0 >> 1)] = u;                   \
            }                                                                 \
        }
        MM_STORE_H(0, a0x, a0y, a0z, a0w)
        MM_STORE_H(1, a1x, a1y, a1z, a1w)
        MM_STORE_H(2, a2x, a2y, a2z, a2w)
        MM_STORE_H(3, a3x, a3y, a3z, a3w)
        #undef MM_STORE_H
        __syncthreads();
    }
}

__global__ __launch_bounds__(256) void k_mm1(const float* __restrict__ W,
                                             const float* __restrict__ b) {
    mm_body_h<20>(g_agg, W, b);
}
__global__ __launch_bounds__(256) void k_mm2(const float* __restrict__ W,
                                             const float* __restrict__ b) {
    mm_body_h<64>(g_agg, W, b);
}

// ---------------- final: (mean @ W3 + b3) @ Wl + bl -> log_softmax -------------
__global__ __launch_bounds__(128) void k_final(const float* __restrict__ W3,
                                               const float* __restrict__ b3,
                                               const float* __restrict__ Wl,
                                               const float* __restrict__ bl,
                                               float* __restrict__ out) {
    int g = blockIdx.x;
    int j = threadIdx.x;
    __shared__ float sp[64];
    __shared__ float sf[128];
    int st = g_start[g], en = g_start[g + 1];
    float inv = 1.0f / fmaxf((float)(en - st), 1.0f);
    if (j < 64) sp[j] = g_psum[g * 64 + j] * inv;
    __syncthreads();
    float f = b3[j];
    #pragma unroll 8
    for (int k = 0; k < 64; k++)
        f = fmaf(sp[k], W3[k * 128 + j], f);
    sf[j] = f;
    __syncthreads();
    if (j < 32) {
        float l = -INFINITY;
        if (j < 14) {
            float acc = bl[j];
            #pragma unroll 8
            for (int k = 0; k < 128; k++)
                acc = fmaf(sf[k], Wl[k * 14 + j], acc);
            l = acc;
        }
        float m = l;
        #pragma unroll
        for (int off = 16; off; off >>= 1)
            m = fmaxf(m, __shfl_xor_sync(0xFFFFFFFFu, m, off));
        float ex = (j < 14) ? expf(l - m) : 0.f;
        float s = ex;
        #pragma unroll
        for (int off = 16; off; off >>= 1)
            s += __shfl_xor_sync(0xFFFFFFFFu, s, off);
        if (j < 14) out[g * 14 + j] = l - m - logf(s);
    }
}

// ---------------- launch ----------------
extern "C" void kernel_launch(void* const* d_in, const int* in_sizes, int n_in,
                              void* d_out, int out_size) {
    const float* x     = (const float*)d_in[0];
    const void*  ei    = d_in[1];
    const void*  batch = d_in[2];
    const float* W1 = (const float*)d_in[3];
    const float* b1 = (const float*)d_in[4];
    const float* W2 = (const float*)d_in[5];
    const float* b2 = (const float*)d_in[6];
    const float* W3 = (const float*)d_in[7];
    const float* b3 = (const float*)d_in[8];
    const float* Wl = (const float*)d_in[9];
    const float* bl = (const float*)d_in[10];
    float* out = (float*)d_out;

    const int TB = 256;
    int nblkN = (N_NODES + TB - 1) / TB;
    int nblkE2 = (N_EDGES / 2 + TB - 1) / TB;
    int nblkW = N_NODES / 8;            // exact: 100000 = 12500 * 8
    int mmGrid = 592;

    k_detect<<<1, 32>>>(ei);                                        // 1
    k_prep<<<(N_NODES * 16 + TB - 1) / TB, TB>>>(x);                // 2
    k_bound<<<nblkN, TB>>>(batch);                                  // 3
    k_passA<<<nblkE2, TB>>>(ei);                                    // 4 <- profiled
    k_scan1<<<SCAN_CHUNKS, 1024>>>();                               // 5
    k_scan2<<<1, 128>>>();                                          // 6
    k_scan3<<<nblkN, TB>>>();                                       // 7
    k_passB<<<nblkE2, TB>>>();                                      // 8

    k_agg20<<<nblkW, TB>>>(x);                                      // 9
    k_mm1<<<mmGrid, TB>>>(W1, b1);                                  // 10
    k_agg64<<<nblkW, TB>>>();                                       // 11
    k_mm2<<<mmGrid, TB>>>(W2, b2);                                  // 12
    k_agg64_pool<<<nblkW, TB>>>(batch);                             // 13
    k_final<<<N_GRAPHS, 128>>>(W3, b3, Wl, bl, out);                // 14
}

// round 11
// speedup vs baseline: 1.0643x; 1.0643x over previous
#include <cuda_runtime.h>
#include <cuda_fp16.h>
#include <math.h>

#define N_NODES 100000
#define N_EDGES 3200000
#define N_GRAPHS 128
#define SCAN_CHUNKS 98            // ceil(100000/1024)

// ---------------- device scratch ----------------
__device__ int   g_is64;
__device__ int   g_cnt[N_NODES];
__device__ float g_dinv[N_NODES];
__device__ int   g_rowptr[N_NODES + 1];
__device__ int   g_cursor[N_NODES];
__device__ int2  g_edge[N_EDGES];           // (src, bitcast weight)
__device__ float g_agg[N_NODES * 64];       // fp32 aggregation output
__device__ __half2 g_h16[N_NODES * 32];     // fp16 hidden features [N,64]
__device__ __half2 g_x16[N_NODES * 16];     // fp16 padded input    [N,32]
__device__ float g_psum[N_GRAPHS * 64];
__device__ int   g_start[N_GRAPHS + 1];
__device__ int   g_bsum[128];
__device__ int   g_boff[128];

// ---------------- helpers ----------------
__device__ __forceinline__ int ld_idx(const void* p, long long i) {
    if (g_is64) return (int)((const long long*)p)[i];
    return ((const int*)p)[i];
}

__device__ __forceinline__ void fma8(float* acc, uint4 v, float w) {
    float2 a = __half22float2(*(__half2*)&v.x);
    float2 b = __half22float2(*(__half2*)&v.y);
    float2 c = __half22float2(*(__half2*)&v.z);
    float2 d = __half22float2(*(__half2*)&v.w);
    acc[0] = fmaf(w, a.x, acc[0]); acc[1] = fmaf(w, a.y, acc[1]);
    acc[2] = fmaf(w, b.x, acc[2]); acc[3] = fmaf(w, b.y, acc[3]);
    acc[4] = fmaf(w, c.x, acc[4]); acc[5] = fmaf(w, c.y, acc[5]);
    acc[6] = fmaf(w, d.x, acc[6]); acc[7] = fmaf(w, d.y, acc[7]);
}

// ---------------- dtype probe ----------------
__global__ void k_detect(const void* p) {
    if (threadIdx.x != 0 || blockIdx.x != 0) return;
    const long long* q = (const long long*)p;
    int ok64 = 1;
    for (int i = 0; i < 256; i++) {
        long long v = q[i];
        if (v < 0 || v >= (long long)N_NODES) { ok64 = 0; break; }
    }
    g_is64 = ok64;
}

// ---------------- prep: zero counters + convert x to padded fp16 [N,32] -------
__global__ void k_prep(const float* __restrict__ x) {
    int i = blockIdx.x * blockDim.x + threadIdx.x;
    if (i < N_NODES) g_cnt[i] = 0;
    if (i < N_GRAPHS * 64) g_psum[i] = 0.f;
    if (i < N_NODES * 16) {
        int n = i >> 4, j = i & 15;
        int f = 2 * j;
        float a = (f < 20) ? x[n * 20 + f] : 0.f;
        float b = (f + 1 < 20) ? x[n * 20 + f + 1] : 0.f;
        g_x16[i] = __floats2half2_rn(a, b);
    }
}

// ---------------- graph boundaries (batch sorted, no atomics) ----------------
__global__ void k_bound(const void* p) {
    int i = blockIdx.x * blockDim.x + threadIdx.x;
    if (i >= N_NODES) return;
    int b = ld_idx(p, i);
    int prev = (i == 0) ? -1 : ld_idx(p, i - 1);
    for (int g = prev + 1; g <= b; g++) g_start[g] = i;
    if (i == N_NODES - 1)
        for (int g = b + 1; g <= N_GRAPHS; g++) g_start[g] = N_NODES;
}

// ---------------- degree count: 4 edges/thread, fire-and-forget atomics -------
__global__ void k_deg(const void* p) {
    int t = blockIdx.x * blockDim.x + threadIdx.x;
    if (t >= N_EDGES / 4) return;
    int d0, d1, d2, d3;
    if (g_is64) {
        const longlong2* q = (const longlong2*)((const long long*)p + N_EDGES);
        longlong2 a = __ldg(&q[2 * t]);
        longlong2 b = __ldg(&q[2 * t + 1]);
        d0 = (int)a.x; d1 = (int)a.y; d2 = (int)b.x; d3 = (int)b.y;
    } else {
        const int4* q = (const int4*)((const int*)p + N_EDGES);
        int4 v = __ldg(&q[t]);
        d0 = v.x; d1 = v.y; d2 = v.z; d3 = v.w;
    }
    atomicAdd(&g_cnt[d0], 1);
    atomicAdd(&g_cnt[d1], 1);
    atomicAdd(&g_cnt[d2], 1);
    atomicAdd(&g_cnt[d3], 1);
}

// ---------------- multi-block scan ----------------
__global__ __launch_bounds__(1024) void k_scan1() {
    int tid = threadIdx.x;
    int lane = tid & 31, wid = tid >> 5;
    int i = blockIdx.x * 1024 + tid;
    int v = (i < N_NODES) ? g_cnt[i] : 0;
    int x = v;
    #pragma unroll
    for (int off = 1; off < 32; off <<= 1) {
        int t = __shfl_up_sync(0xFFFFFFFFu, x, off);
        if (lane >= off) x += t;
    }
    __shared__ int ws[32];
    if (lane == 31) ws[wid] = x;
    __syncthreads();
    if (wid == 0) {
        int y = ws[lane];
        #pragma unroll
        for (int off = 1; off < 32; off <<= 1) {
            int t = __shfl_up_sync(0xFFFFFFFFu, y, off);
            if (lane >= off) y += t;
        }
        ws[lane] = y;
    }
    __syncthreads();
    int incl = x + (wid > 0 ? ws[wid - 1] : 0);
    if (i < N_NODES) g_rowptr[i] = incl - v;
    if (tid == 1023) g_bsum[blockIdx.x] = incl;
}

__global__ void k_scan2() {
    __shared__ int sh[128];
    int t = threadIdx.x;
    int v = (t < SCAN_CHUNKS) ? g_bsum[t] : 0;
    sh[t] = v;
    __syncthreads();
    #pragma unroll
    for (int off = 1; off < 128; off <<= 1) {
        int u = (t >= off) ? sh[t - off] : 0;
        __syncthreads();
        sh[t] += u;
        __syncthreads();
    }
    if (t < SCAN_CHUNKS) g_boff[t] = sh[t] - v;
    if (t == 127) g_rowptr[N_NODES] = sh[127];
}

__global__ void k_scan3() {
    int i = blockIdx.x * blockDim.x + threadIdx.x;
    if (i >= N_NODES) return;
    int r = g_rowptr[i] + g_boff[i >> 10];
    g_rowptr[i] = r;
    g_cursor[i] = r;
    g_dinv[i] = rsqrtf((float)g_cnt[i] + 1.0f);
}

// ---------------- CSR fill: 2 edges/thread ----------------
__global__ void k_fill(const void* p) {
    int t = blockIdx.x * blockDim.x + threadIdx.x;
    if (t >= N_EDGES / 2) return;
    int s0, s1, d0, d1;
    if (g_is64) {
        const longlong2* qs = (const longlong2*)p;
        const longlong2* qd = (const longlong2*)((const long long*)p + N_EDGES);
        longlong2 sv = __ldg(&qs[t]);
        longlong2 dv = __ldg(&qd[t]);
        s0 = (int)sv.x; s1 = (int)sv.y;
        d0 = (int)dv.x; d1 = (int)dv.y;
    } else {
        const int2* qs = (const int2*)p;
        const int2* qd = (const int2*)((const int*)p + N_EDGES);
        int2 sv = __ldg(&qs[t]);
        int2 dv = __ldg(&qd[t]);
        s0 = sv.x; s1 = sv.y;
        d0 = dv.x; d1 = dv.y;
    }
    int p0 = atomicAdd(&g_cursor[d0], 1);
    g_edge[p0] = make_int2(s0, __float_as_int(g_dinv[s0] * g_dinv[d0]));
    int p1 = atomicAdd(&g_cursor[d1], 1);
    g_edge[p1] = make_int2(s1, __float_as_int(g_dinv[s1] * g_dinv[d1]));
}

// ---------------- aggregation F=20: 8 edges per LDG.128 ------------------------
// Row of g_x16 = 64B = 4 uint4. Lane group eg=lane>>2 (8 groups) owns edge
// e+eg; fl=lane&3 owns 16B feature chunk (features fl*8..fl*8+7).
__global__ __launch_bounds__(256) void k_agg20(const float* __restrict__ x) {
    int i = (blockIdx.x * blockDim.x + threadIdx.x) >> 5;
    int lane = threadIdx.x & 31;
    int eg = lane >> 2;
    int fl = lane & 3;
    int beg = g_rowptr[i], end = g_rowptr[i + 1];
    const uint4* x4 = (const uint4*)g_x16;      // row i -> x4[i*4 + fl]
    float acc[8];
    #pragma unroll
    for (int j = 0; j < 8; j++) acc[j] = 0.f;
    for (int e = beg; e < end; e += 16) {
        int e0 = e + eg, e1 = e + 8 + eg;
        int2 r0 = g_edge[(e0 < end) ? e0 : beg];
        int2 r1 = g_edge[(e1 < end) ? e1 : beg];
        float w0 = (e0 < end) ? __int_as_float(r0.y) : 0.f;
        float w1 = (e1 < end) ? __int_as_float(r1.y) : 0.f;
        uint4 v0 = __ldg(&x4[r0.x * 4 + fl]);
        uint4 v1 = __ldg(&x4[r1.x * 4 + fl]);
        fma8(acc, v0, w0);
        fma8(acc, v1, w1);
    }
    #pragma unroll
    for (int j = 0; j < 8; j++) {
        acc[j] += __shfl_xor_sync(0xFFFFFFFFu, acc[j], 4);
        acc[j] += __shfl_xor_sync(0xFFFFFFFFu, acc[j], 8);
        acc[j] += __shfl_xor_sync(0xFFFFFFFFu, acc[j], 16);
    }
    if (eg == 0 && fl < 3) {
        float di = g_dinv[i];
        float dd = di * di;
        int f0 = fl * 8;
        #pragma unroll
        for (int j = 0; j < 8; j++) {
            int f = f0 + j;
            if (f < 20) acc[j] = fmaf(dd, x[i * 20 + f], acc[j]);
        }
        float4 o1 = make_float4(acc[0], acc[1], acc[2], acc[3]);
        *(float4*)&g_agg[i * 20 + f0] = o1;
        if (fl < 2) {
            float4 o2 = make_float4(acc[4], acc[5], acc[6], acc[7]);
            *(float4*)&g_agg[i * 20 + f0 + 4] = o2;
        }
    }
}

// ---------------- aggregation F=64: 4 edges per LDG.128 ------------------------
// Row of g_h16 = 128B = 8 uint4. eg=lane>>3 (4 groups) owns edge e+eg;
// fl=lane&7 owns features fl*8..fl*8+7.
template <bool POOL>
__device__ __forceinline__ void agg64_body(const void* batch) {
    __shared__ float sacc[64];
    __shared__ int sg;
    int i = (blockIdx.x * blockDim.x + threadIdx.x) >> 5;   // grid exact
    int lane = threadIdx.x & 31;
    int eg = lane >> 3;
    int fl = lane & 7;
    if (POOL) {
        if (threadIdx.x < 64) sacc[threadIdx.x] = 0.f;
        if (threadIdx.x == 0) sg = ld_idx(batch, (blockIdx.x * blockDim.x) >> 5);
        __syncthreads();
    }
    int beg = g_rowptr[i], end = g_rowptr[i + 1];
    const uint4* h4 = (const uint4*)g_h16;      // row i -> h4[i*8 + fl]
    float acc[8];
    #pragma unroll
    for (int j = 0; j < 8; j++) acc[j] = 0.f;
    for (int e = beg; e < end; e += 8) {
        int e0 = e + eg, e1 = e + 4 + eg;
        int2 r0 = g_edge[(e0 < end) ? e0 : beg];
        int2 r1 = g_edge[(e1 < end) ? e1 : beg];
        float w0 = (e0 < end) ? __int_as_float(r0.y) : 0.f;
        float w1 = (e1 < end) ? __int_as_float(r1.y) : 0.f;
        uint4 v0 = __ldg(&h4[r0.x * 8 + fl]);
        uint4 v1 = __ldg(&h4[r1.x * 8 + fl]);
        fma8(acc, v0, w0);
        fma8(acc, v1, w1);
    }
    #pragma unroll
    for (int j = 0; j < 8; j++) {
        acc[j] += __shfl_xor_sync(0xFFFFFFFFu, acc[j], 8);
        acc[j] += __shfl_xor_sync(0xFFFFFFFFu, acc[j], 16);
    }
    // self-loop (after reduction; every lane holds the full sum for its chunk)
    {
        float di = g_dinv[i];
        float dd = di * di;
        uint4 sv = h4[i * 8 + fl];
        fma8(acc, sv, dd);
    }
    if (!POOL) {
        if (eg == 0) {
            *(float4*)&g_agg[i * 64 + fl * 8]     = make_float4(acc[0], acc[1], acc[2], acc[3]);
            *(float4*)&g_agg[i * 64 + fl * 8 + 4] = make_float4(acc[4], acc[5], acc[6], acc[7]);
        }
    } else {
        int b = ld_idx(batch, i);
        int uniform = __syncthreads_and(b == sg);
        if (uniform) {
            if (eg == 0) {
                #pragma unroll
                for (int j = 0; j < 8; j++)
                    atomicAdd(&sacc[fl * 8 + j], acc[j]);
            }
            __syncthreads();
            if (threadIdx.x < 64)
                atomicAdd(&g_psum[sg * 64 + threadIdx.x], sacc[threadIdx.x]);
        } else {
            if (eg == 0) {
                #pragma unroll
                for (int j = 0; j < 8; j++)
                    atomicAdd(&g_psum[b * 64 + fl * 8 + j], acc[j]);
            }
        }
    }
}

__global__ __launch_bounds__(256) void k_agg64() { agg64_body<false>(nullptr); }
__global__ __launch_bounds__(256) void k_agg64_pool(const void* batch) {
    agg64_body<true>(batch);
}

// ---------------- FMA-bound matmul: 64-node tile, 4x4 outer product -----------
template <int FIN>
__device__ __forceinline__ void mm_body_h(const float* __restrict__ in,
                                          const float* __restrict__ W,
                                          const float* __restrict__ b) {
    constexpr int FOUT = 64;
    constexpr int NT = 64;
    __shared__ float Ws[FIN * FOUT];
    __shared__ float bs[FOUT];
    __shared__ float rT[FIN][NT + 4];
    for (int k = threadIdx.x; k < FIN * FOUT; k += 256) Ws[k] = W[k];
    if (threadIdx.x < FOUT) bs[threadIdx.x] = b[threadIdx.x];
    int cg = threadIdx.x & 15;
    int ng = threadIdx.x >> 4;
    int c0 = cg * 4, nb = ng * 4;
    const int ntiles = (N_NODES + NT - 1) / NT;
    for (int tile = blockIdx.x; tile < ntiles; tile += gridDim.x) {
        int n0 = tile * NT;
        for (int idx = threadIdx.x; idx < NT * FIN; idx += 256) {
            int n = idx / FIN, k = idx - n * FIN;
            int node = n0 + n;
            rT[k][n] = (node < N_NODES) ? in[node * FIN + k] : 0.f;
        }
        __syncthreads();
        float a0x = bs[c0], a0y = bs[c0+1], a0z = bs[c0+2], a0w = bs[c0+3];
        float a1x = a0x, a1y = a0y, a1z = a0z, a1w = a0w;
        float a2x = a0x, a2y = a0y, a2z = a0z, a2w = a0w;
        float a3x = a0x, a3y = a0y, a3z = a0z, a3w = a0w;
        #pragma unroll 4
        for (int k = 0; k < FIN; k++) {
            float4 rv = *(const float4*)&rT[k][nb];
            float4 wv = *(const float4*)&Ws[k * FOUT + c0];
            a0x = fmaf(rv.x, wv.x, a0x); a0y = fmaf(rv.x, wv.y, a0y);
            a0z = fmaf(rv.x, wv.z, a0z); a0w = fmaf(rv.x, wv.w, a0w);
            a1x = fmaf(rv.y, wv.x, a1x); a1y = fmaf(rv.y, wv.y, a1y);
            a1z = fmaf(rv.y, wv.z, a1z); a1w = fmaf(rv.y, wv.w, a1w);
            a2x = fmaf(rv.z, wv.x, a2x); a2y = fmaf(rv.z, wv.y, a2y);
            a2z = fmaf(rv.z, wv.z, a2z); a2w = fmaf(rv.z, wv.w, a2w);
            a3x = fmaf(rv.w, wv.x, a3x); a3y = fmaf(rv.w, wv.y, a3y);
            a3z = fmaf(rv.w, wv.z, a3z); a3w = fmaf(rv.w, wv.w, a3w);
        }
        #define MM_STORE_H(NI, AX, AY, AZ, AW)                                \
        {                                                                     \
            int node = n0 + nb + NI;                                          \
            if (node < N_NODES) {                                             \
                __half2 h01 = __floats2half2_rn(fmaxf(AX, 0.f), fmaxf(AY, 0.f)); \
                __half2 h23 = __floats2half2_rn(fmaxf(AZ, 0.f), fmaxf(AW, 0.f)); \
                uint2 u;                                                      \
                u.x = *reinterpret_cast<unsigned*>(&h01);                     \
                u.y = *reinterpret_cast<unsigned*>(&h23);                     \
                *(uint2*)&g_h16[node * 32 + (c0 >> 1)] = u;                   \
            }                                                                 \
        }
        MM_STORE_H(0, a0x, a0y, a0z, a0w)
        MM_STORE_H(1, a1x, a1y, a1z, a1w)
        MM_STORE_H(2, a2x, a2y, a2z, a2w)
        MM_STORE_H(3, a3x, a3y, a3z, a3w)
        #undef MM_STORE_H
        __syncthreads();
    }
}

__global__ __launch_bounds__(256) void k_mm1(const float* __restrict__ W,
                                             const float* __restrict__ b) {
    mm_body_h<20>(g_agg, W, b);
}
__global__ __launch_bounds__(256) void k_mm2(const float* __restrict__ W,
                                             const float* __restrict__ b) {
    mm_body_h<64>(g_agg, W, b);
}

// ---------------- final: (mean @ W3 + b3) @ Wl + bl -> log_softmax -------------
__global__ __launch_bounds__(128) void k_final(const float* __restrict__ W3,
                                               const float* __restrict__ b3,
                                               const float* __restrict__ Wl,
                                               const float* __restrict__ bl,
                                               float* __restrict__ out) {
    int g = blockIdx.x;
    int j = threadIdx.x;
    __shared__ float sp[64];
    __shared__ float sf[128];
    int st = g_start[g], en = g_start[g + 1];
    float inv = 1.0f / fmaxf((float)(en - st), 1.0f);
    if (j < 64) sp[j] = g_psum[g * 64 + j] * inv;
    __syncthreads();
    float f = b3[j];
    #pragma unroll 8
    for (int k = 0; k < 64; k++)
        f = fmaf(sp[k], W3[k * 128 + j], f);
    sf[j] = f;
    __syncthreads();
    if (j < 32) {
        float l = -INFINITY;
        if (j < 14) {
            float acc = bl[j];
            #pragma unroll 8
            for (int k = 0; k < 128; k++)
                acc = fmaf(sf[k], Wl[k * 14 + j], acc);
            l = acc;
        }
        float m = l;
        #pragma unroll
        for (int off = 16; off; off >>= 1)
            m = fmaxf(m, __shfl_xor_sync(0xFFFFFFFFu, m, off));
        float ex = (j < 14) ? expf(l - m) : 0.f;
        float s = ex;
        #pragma unroll
        for (int off = 16; off; off >>= 1)
            s += __shfl_xor_sync(0xFFFFFFFFu, s, off);
        if (j < 14) out[g * 14 + j] = l - m - logf(s);
    }
}

// ---------------- launch ----------------
extern "C" void kernel_launch(void* const* d_in, const int* in_sizes, int n_in,
                              void* d_out, int out_size) {
    const float* x     = (const float*)d_in[0];
    const void*  ei    = d_in[1];
    const void*  batch = d_in[2];
    const float* W1 = (const float*)d_in[3];
    const float* b1 = (const float*)d_in[4];
    const float* W2 = (const float*)d_in[5];
    const float* b2 = (const float*)d_in[6];
    const float* W3 = (const float*)d_in[7];
    const float* b3 = (const float*)d_in[8];
    const float* Wl = (const float*)d_in[9];
    const float* bl = (const float*)d_in[10];
    float* out = (float*)d_out;

    const int TB = 256;
    int nblkN = (N_NODES + TB - 1) / TB;
    int nblkW = N_NODES / 8;            // exact: 100000 = 12500 * 8
    int mmGrid = 592;

    k_detect<<<1, 32>>>(ei);                                        // 1
    k_prep<<<(N_NODES * 16 + TB - 1) / TB, TB>>>(x);                // 2
    k_bound<<<nblkN, TB>>>(batch);                                  // 3
    k_deg<<<(N_EDGES / 4 + TB - 1) / TB, TB>>>(ei);                 // 4 <- profiled
    k_scan1<<<SCAN_CHUNKS, 1024>>>();                               // 5
    k_scan2<<<1, 128>>>();                                          // 6
    k_scan3<<<nblkN, TB>>>();                                       // 7
    k_fill<<<(N_EDGES / 2 + TB - 1) / TB, TB>>>(ei);                // 8

    k_agg20<<<nblkW, TB>>>(x);                                      // 9
    k_mm1<<<mmGrid, TB>>>(W1, b1);                                  // 10
    k_agg64<<<nblkW, TB>>>();                                       // 11
    k_mm2<<<mmGrid, TB>>>(W2, b2);                                  // 12
    k_agg64_pool<<<nblkW, TB>>>(batch);                             // 13
    k_final<<<N_GRAPHS, 128>>>(W3, b3, Wl, bl, out);                // 14
}

// round 12
// speedup vs baseline: 1.1222x; 1.0544x over previous
#include <cuda_runtime.h>
#include <cuda_fp16.h>
#include <math.h>

#define N_NODES 100000
#define N_EDGES 3200000
#define N_GRAPHS 128
#define SCAN_CHUNKS 98            // ceil(100000/1024)

// ---------------- device scratch ----------------
__device__ int   g_is64;
__device__ int   g_cnt[N_NODES];
__device__ float g_dinv[N_NODES];
__device__ int   g_rowptr[N_NODES + 1];
__device__ int   g_cursor[N_NODES];
__device__ int   g_edge[N_EDGES];           // src only (weights reassociated away)
__device__ float g_agg[N_NODES * 64];       // fp32 aggregation output
__device__ uint4 g_h16[N_NODES * 8];        // fp16 dinv-scaled hidden [N,64]
__device__ uint4 g_x16[N_NODES * 4];        // fp16 dinv-scaled padded x [N,32]
__device__ float g_psum[N_GRAPHS * 64];
__device__ int   g_start[N_GRAPHS + 1];
__device__ int   g_bsum[128];
__device__ int   g_boff[128];

// ---------------- helpers ----------------
__device__ __forceinline__ int ld_idx(const void* p, long long i) {
    if (g_is64) return (int)((const long long*)p)[i];
    return ((const int*)p)[i];
}

__device__ __forceinline__ void fma8(float* acc, uint4 v, float w) {
    float2 a = __half22float2(*(__half2*)&v.x);
    float2 b = __half22float2(*(__half2*)&v.y);
    float2 c = __half22float2(*(__half2*)&v.z);
    float2 d = __half22float2(*(__half2*)&v.w);
    acc[0] = fmaf(w, a.x, acc[0]); acc[1] = fmaf(w, a.y, acc[1]);
    acc[2] = fmaf(w, b.x, acc[2]); acc[3] = fmaf(w, b.y, acc[3]);
    acc[4] = fmaf(w, c.x, acc[4]); acc[5] = fmaf(w, c.y, acc[5]);
    acc[6] = fmaf(w, d.x, acc[6]); acc[7] = fmaf(w, d.y, acc[7]);
}

// ---------------- prep: dtype probe (thread 0) + zero counters ----------------
__global__ void k_prep(const void* p) {
    int i = blockIdx.x * blockDim.x + threadIdx.x;
    if (i == 0) {
        const long long* q = (const long long*)p;
        int ok64 = 1;
        for (int k = 0; k < 256; k++) {
            long long v = q[k];
            if (v < 0 || v >= (long long)N_NODES) { ok64 = 0; break; }
        }
        g_is64 = ok64;
    }
    if (i < N_NODES) g_cnt[i] = 0;
    if (i < N_GRAPHS * 64) g_psum[i] = 0.f;
}

// ---------------- graph boundaries (batch sorted, no atomics) ----------------
__global__ void k_bound(const void* p) {
    int i = blockIdx.x * blockDim.x + threadIdx.x;
    if (i >= N_NODES) return;
    int b = ld_idx(p, i);
    int prev = (i == 0) ? -1 : ld_idx(p, i - 1);
    for (int g = prev + 1; g <= b; g++) g_start[g] = i;
    if (i == N_NODES - 1)
        for (int g = b + 1; g <= N_GRAPHS; g++) g_start[g] = N_NODES;
}

// ---------------- degree count: 4 edges/thread, fire-and-forget atomics -------
__global__ void k_deg(const void* p) {
    int t = blockIdx.x * blockDim.x + threadIdx.x;
    if (t >= N_EDGES / 4) return;
    int d0, d1, d2, d3;
    if (g_is64) {
        const longlong2* q = (const longlong2*)((const long long*)p + N_EDGES);
        longlong2 a = __ldg(&q[2 * t]);
        longlong2 b = __ldg(&q[2 * t + 1]);
        d0 = (int)a.x; d1 = (int)a.y; d2 = (int)b.x; d3 = (int)b.y;
    } else {
        const int4* q = (const int4*)((const int*)p + N_EDGES);
        int4 v = __ldg(&q[t]);
        d0 = v.x; d1 = v.y; d2 = v.z; d3 = v.w;
    }
    atomicAdd(&g_cnt[d0], 1);
    atomicAdd(&g_cnt[d1], 1);
    atomicAdd(&g_cnt[d2], 1);
    atomicAdd(&g_cnt[d3], 1);
}

// ---------------- multi-block scan ----------------
__global__ __launch_bounds__(1024) void k_scan1() {
    int tid = threadIdx.x;
    int lane = tid & 31, wid = tid >> 5;
    int i = blockIdx.x * 1024 + tid;
    int v = (i < N_NODES) ? g_cnt[i] : 0;
    int x = v;
    #pragma unroll
    for (int off = 1; off < 32; off <<= 1) {
        int t = __shfl_up_sync(0xFFFFFFFFu, x, off);
        if (lane >= off) x += t;
    }
    __shared__ int ws[32];
    if (lane == 31) ws[wid] = x;
    __syncthreads();
    if (wid == 0) {
        int y = ws[lane];
        #pragma unroll
        for (int off = 1; off < 32; off <<= 1) {
            int t = __shfl_up_sync(0xFFFFFFFFu, y, off);
            if (lane >= off) y += t;
        }
        ws[lane] = y;
    }
    __syncthreads();
    int incl = x + (wid > 0 ? ws[wid - 1] : 0);
    if (i < N_NODES) g_rowptr[i] = incl - v;
    if (tid == 1023) g_bsum[blockIdx.x] = incl;
}

__global__ void k_scan2() {
    __shared__ int sh[128];
    int t = threadIdx.x;
    int v = (t < SCAN_CHUNKS) ? g_bsum[t] : 0;
    sh[t] = v;
    __syncthreads();
    #pragma unroll
    for (int off = 1; off < 128; off <<= 1) {
        int u = (t >= off) ? sh[t - off] : 0;
        __syncthreads();
        sh[t] += u;
        __syncthreads();
    }
    if (t < SCAN_CHUNKS) g_boff[t] = sh[t] - v;
    if (t == 127) g_rowptr[N_NODES] = sh[127];
}

// ---------------- scan3: finalize rowptr/cursor/dinv + build x~ = dinv*x ------
__global__ void k_scan3(const float* __restrict__ x) {
    int i = blockIdx.x * blockDim.x + threadIdx.x;
    if (i >= N_NODES) return;
    int r = g_rowptr[i] + g_boff[i >> 10];
    g_rowptr[i] = r;
    g_cursor[i] = r;
    float di = rsqrtf((float)g_cnt[i] + 1.0f);
    g_dinv[i] = di;
    // x~ row: 20 floats * di -> fp16, padded to 32 halves (64B)
    const float4* xr = (const float4*)(x + i * 20);   // 80B row, 16B aligned
    float tmp[20];
    #pragma unroll
    for (int q = 0; q < 5; q++) {
        float4 v = __ldg(&xr[q]);
        tmp[4*q] = v.x; tmp[4*q+1] = v.y; tmp[4*q+2] = v.z; tmp[4*q+3] = v.w;
    }
    unsigned h[16];
    #pragma unroll
    for (int q = 0; q < 10; q++) {
        __half2 hh = __floats2half2_rn(di * tmp[2*q], di * tmp[2*q+1]);
        h[q] = *(unsigned*)&hh;
    }
    #pragma unroll
    for (int q = 10; q < 16; q++) h[q] = 0u;
    uint4* dst = &g_x16[i * 4];
    dst[0] = make_uint4(h[0], h[1], h[2], h[3]);
    dst[1] = make_uint4(h[4], h[5], h[6], h[7]);
    dst[2] = make_uint4(h[8], h[9], h[10], h[11]);
    dst[3] = make_uint4(h[12], h[13], h[14], h[15]);
}

// ---------------- CSR fill: src only, no weight computation ----------------
__global__ void k_fill(const void* p) {
    int t = blockIdx.x * blockDim.x + threadIdx.x;
    if (t >= N_EDGES / 2) return;
    int s0, s1, d0, d1;
    if (g_is64) {
        const longlong2* qs = (const longlong2*)p;
        const longlong2* qd = (const longlong2*)((const long long*)p + N_EDGES);
        longlong2 sv = __ldg(&qs[t]);
        longlong2 dv = __ldg(&qd[t]);
        s0 = (int)sv.x; s1 = (int)sv.y;
        d0 = (int)dv.x; d1 = (int)dv.y;
    } else {
        const int2* qs = (const int2*)p;
        const int2* qd = (const int2*)((const int*)p + N_EDGES);
        int2 sv = __ldg(&qs[t]);
        int2 dv = __ldg(&qd[t]);
        s0 = sv.x; s1 = sv.y;
        d0 = dv.x; d1 = dv.y;
    }
    int p0 = atomicAdd(&g_cursor[d0], 1);
    g_edge[p0] = s0;
    int p1 = atomicAdd(&g_cursor[d1], 1);
    g_edge[p1] = s1;
}

// ---------------- aggregation F=20: 8 edges per LDG.128 on x~ ------------------
__global__ __launch_bounds__(256) void k_agg20() {
    int i = (blockIdx.x * blockDim.x + threadIdx.x) >> 5;
    int lane = threadIdx.x & 31;
    int eg = lane >> 2;
    int fl = lane & 3;
    int beg = g_rowptr[i], end = g_rowptr[i + 1];
    float acc[8];
    #pragma unroll
    for (int j = 0; j < 8; j++) acc[j] = 0.f;
    for (int e = beg; e < end; e += 16) {
        int e0 = e + eg, e1 = e + 8 + eg;
        int s0 = g_edge[(e0 < end) ? e0 : beg];
        int s1 = g_edge[(e1 < end) ? e1 : beg];
        float w0 = (e0 < end) ? 1.f : 0.f;
        float w1 = (e1 < end) ? 1.f : 0.f;
        uint4 v0 = __ldg(&g_x16[s0 * 4 + fl]);
        uint4 v1 = __ldg(&g_x16[s1 * 4 + fl]);
        fma8(acc, v0, w0);
        fma8(acc, v1, w1);
    }
    #pragma unroll
    for (int j = 0; j < 8; j++) {
        acc[j] += __shfl_xor_sync(0xFFFFFFFFu, acc[j], 4);
        acc[j] += __shfl_xor_sync(0xFFFFFFFFu, acc[j], 8);
        acc[j] += __shfl_xor_sync(0xFFFFFFFFu, acc[j], 16);
    }
    if (eg == 0 && fl < 3) {
        uint4 sv = g_x16[i * 4 + fl];      // self-loop: + x~_i
        fma8(acc, sv, 1.f);
        float di = g_dinv[i];
        #pragma unroll
        for (int j = 0; j < 8; j++) acc[j] *= di;
        int f0 = fl * 8;
        *(float4*)&g_agg[i * 20 + f0] = make_float4(acc[0], acc[1], acc[2], acc[3]);
        if (fl < 2)
            *(float4*)&g_agg[i * 20 + f0 + 4] = make_float4(acc[4], acc[5], acc[6], acc[7]);
    }
}

// ---------------- aggregation F=64: 4 edges per LDG.128 on h~ ------------------
template <bool POOL>
__device__ __forceinline__ void agg64_body(const void* batch) {
    __shared__ float sacc[64];
    __shared__ int sg;
    int i = (blockIdx.x * blockDim.x + threadIdx.x) >> 5;   // grid exact
    int lane = threadIdx.x & 31;
    int eg = lane >> 3;
    int fl = lane & 7;
    if (POOL) {
        if (threadIdx.x < 64) sacc[threadIdx.x] = 0.f;
        if (threadIdx.x == 0) sg = ld_idx(batch, (blockIdx.x * blockDim.x) >> 5);
        __syncthreads();
    }
    int beg = g_rowptr[i], end = g_rowptr[i + 1];
    float acc[8];
    #pragma unroll
    for (int j = 0; j < 8; j++) acc[j] = 0.f;
    for (int e = beg; e < end; e += 8) {
        int e0 = e + eg, e1 = e + 4 + eg;
        int s0 = g_edge[(e0 < end) ? e0 : beg];
        int s1 = g_edge[(e1 < end) ? e1 : beg];
        float w0 = (e0 < end) ? 1.f : 0.f;
        float w1 = (e1 < end) ? 1.f : 0.f;
        uint4 v0 = __ldg(&g_h16[s0 * 8 + fl]);
        uint4 v1 = __ldg(&g_h16[s1 * 8 + fl]);
        fma8(acc, v0, w0);
        fma8(acc, v1, w1);
    }
    #pragma unroll
    for (int j = 0; j < 8; j++) {
        acc[j] += __shfl_xor_sync(0xFFFFFFFFu, acc[j], 8);
        acc[j] += __shfl_xor_sync(0xFFFFFFFFu, acc[j], 16);
    }
    // self-loop + final dinv_i scale (all lanes hold full sums for their chunk)
    {
        uint4 sv = g_h16[i * 8 + fl];
        fma8(acc, sv, 1.f);
        float di = g_dinv[i];
        #pragma unroll
        for (int j = 0; j < 8; j++) acc[j] *= di;
    }
    if (!POOL) {
        if (eg == 0) {
            *(float4*)&g_agg[i * 64 + fl * 8]     = make_float4(acc[0], acc[1], acc[2], acc[3]);
            *(float4*)&g_agg[i * 64 + fl * 8 + 4] = make_float4(acc[4], acc[5], acc[6], acc[7]);
        }
    } else {
        int b = ld_idx(batch, i);
        int uniform = __syncthreads_and(b == sg);
        if (uniform) {
            if (eg == 0) {
                #pragma unroll
                for (int j = 0; j < 8; j++)
                    atomicAdd(&sacc[fl * 8 + j], acc[j]);
            }
            __syncthreads();
            if (threadIdx.x < 64)
                atomicAdd(&g_psum[sg * 64 + threadIdx.x], sacc[threadIdx.x]);
        } else {
            if (eg == 0) {
                #pragma unroll
                for (int j = 0; j < 8; j++)
                    atomicAdd(&g_psum[b * 64 + fl * 8 + j], acc[j]);
            }
        }
    }
}

__global__ __launch_bounds__(256) void k_agg64() { agg64_body<false>(nullptr); }
__global__ __launch_bounds__(256) void k_agg64_pool(const void* batch) {
    agg64_body<true>(batch);
}

// ---------------- matmul: out stored as h~ = dinv * relu(in@W + b), fp16 ------
template <int FIN>
__device__ __forceinline__ void mm_body_h(const float* __restrict__ in,
                                          const float* __restrict__ W,
                                          const float* __restrict__ b) {
    constexpr int FOUT = 64;
    constexpr int NT = 64;
    __shared__ float Ws[FIN * FOUT];
    __shared__ float bs[FOUT];
    __shared__ float rT[FIN][NT + 4];
    for (int k = threadIdx.x; k < FIN * FOUT; k += 256) Ws[k] = W[k];
    if (threadIdx.x < FOUT) bs[threadIdx.x] = b[threadIdx.x];
    int cg = threadIdx.x & 15;
    int ng = threadIdx.x >> 4;
    int c0 = cg * 4, nb = ng * 4;
    const int ntiles = (N_NODES + NT - 1) / NT;
    for (int tile = blockIdx.x; tile < ntiles; tile += gridDim.x) {
        int n0 = tile * NT;
        for (int idx = threadIdx.x; idx < NT * FIN; idx += 256) {
            int n = idx / FIN, k = idx - n * FIN;
            int node = n0 + n;
            rT[k][n] = (node < N_NODES) ? in[node * FIN + k] : 0.f;
        }
        __syncthreads();
        float a0x = bs[c0], a0y = bs[c0+1], a0z = bs[c0+2], a0w = bs[c0+3];
        float a1x = a0x, a1y = a0y, a1z = a0z, a1w = a0w;
        float a2x = a0x, a2y = a0y, a2z = a0z, a2w = a0w;
        float a3x = a0x, a3y = a0y, a3z = a0z, a3w = a0w;
        #pragma unroll 4
        for (int k = 0; k < FIN; k++) {
            float4 rv = *(const float4*)&rT[k][nb];
            float4 wv = *(const float4*)&Ws[k * FOUT + c0];
            a0x = fmaf(rv.x, wv.x, a0x); a0y = fmaf(rv.x, wv.y, a0y);
            a0z = fmaf(rv.x, wv.z, a0z); a0w = fmaf(rv.x, wv.w, a0w);
            a1x = fmaf(rv.y, wv.x, a1x); a1y = fmaf(rv.y, wv.y, a1y);
            a1z = fmaf(rv.y, wv.z, a1z); a1w = fmaf(rv.y, wv.w, a1w);
            a2x = fmaf(rv.z, wv.x, a2x); a2y = fmaf(rv.z, wv.y, a2y);
            a2z = fmaf(rv.z, wv.z, a2z); a2w = fmaf(rv.z, wv.w, a2w);
            a3x = fmaf(rv.w, wv.x, a3x); a3y = fmaf(rv.w, wv.y, a3y);
            a3z = fmaf(rv.w, wv.z, a3z); a3w = fmaf(rv.w, wv.w, a3w);
        }
        #define MM_STORE_H(NI, AX, AY, AZ, AW)                                 \
        {                                                                      \
            int node = n0 + nb + NI;                                           \
            if (node < N_NODES) {                                              \
                float di = g_dinv[node];                                       \
                __half2 h01 = __floats2half2_rn(di * fmaxf(AX, 0.f),           \
                                                di * fmaxf(AY, 0.f));          \
                __half2 h23 = __floats2half2_rn(di * fmaxf(AZ, 0.f),           \
                                                di * fmaxf(AW, 0.f));          \
                uint2 u;                                                       \
                u.x = *reinterpret_cast<unsigned*>(&h01);                      \
                u.y = *reinterpret_cast<unsigned*>(&h23);                      \
                ((uint2*)g_h16)[node * 16 + (c0 >> 2)] = u;                    \
            }                                                                  \
        }
        MM_STORE_H(0, a0x, a0y, a0z, a0w)
        MM_STORE_H(1, a1x, a1y, a1z, a1w)
        MM_STORE_H(2, a2x, a2y, a2z, a2w)
        MM_STORE_H(3, a3x, a3y, a3z, a3w)
        #undef MM_STORE_H
        __syncthreads();
    }
}

__global__ __launch_bounds__(256) void k_mm1(const float* __restrict__ W,
                                             const float* __restrict__ b) {
    mm_body_h<20>(g_agg, W, b);
}
__global__ __launch_bounds__(256) void k_mm2(const float* __restrict__ W,
                                             const float* __restrict__ b) {
    mm_body_h<64>(g_agg, W, b);
}

// ---------------- final: (mean @ W3 + b3) @ Wl + bl -> log_softmax -------------
__global__ __launch_bounds__(128) void k_final(const float* __restrict__ W3,
                                               const float* __restrict__ b3,
                                               const float* __restrict__ Wl,
                                               const float* __restrict__ bl,
                                               float* __restrict__ out) {
    int g = blockIdx.x;
    int j = threadIdx.x;
    __shared__ float sp[64];
    __shared__ float sf[128];
    int st = g_start[g], en = g_start[g + 1];
    float inv = 1.0f / fmaxf((float)(en - st), 1.0f);
    if (j < 64) sp[j] = g_psum[g * 64 + j] * inv;
    __syncthreads();
    float f = b3[j];
    #pragma unroll 8
    for (int k = 0; k < 64; k++)
        f = fmaf(sp[k], W3[k * 128 + j], f);
    sf[j] = f;
    __syncthreads();
    if (j < 32) {
        float l = -INFINITY;
        if (j < 14) {
            float acc = bl[j];
            #pragma unroll 8
            for (int k = 0; k < 128; k++)
                acc = fmaf(sf[k], Wl[k * 14 + j], acc);
            l = acc;
        }
        float m = l;
        #pragma unroll
        for (int off = 16; off; off >>= 1)
            m = fmaxf(m, __shfl_xor_sync(0xFFFFFFFFu, m, off));
        float ex = (j < 14) ? expf(l - m) : 0.f;
        float s = ex;
        #pragma unroll
        for (int off = 16; off; off >>= 1)
            s += __shfl_xor_sync(0xFFFFFFFFu, s, off);
        if (j < 14) out[g * 14 + j] = l - m - logf(s);
    }
}

// ---------------- launch ----------------
extern "C" void kernel_launch(void* const* d_in, const int* in_sizes, int n_in,
                              void* d_out, int out_size) {
    const float* x     = (const float*)d_in[0];
    const void*  ei    = d_in[1];
    const void*  batch = d_in[2];
    const float* W1 = (const float*)d_in[3];
    const float* b1 = (const float*)d_in[4];
    const float* W2 = (const float*)d_in[5];
    const float* b2 = (const float*)d_in[6];
    const float* W3 = (const float*)d_in[7];
    const float* b3 = (const float*)d_in[8];
    const float* Wl = (const float*)d_in[9];
    const float* bl = (const float*)d_in[10];
    float* out = (float*)d_out;

    const int TB = 256;
    int nblkN = (N_NODES + TB - 1) / TB;
    int nblkW = N_NODES / 8;            // exact: 100000 = 12500 * 8
    int mmGrid = 592;

    k_prep<<<nblkN, TB>>>(ei);                                      // 1
    k_bound<<<nblkN, TB>>>(batch);                                  // 2
    k_deg<<<(N_EDGES / 4 + TB - 1) / TB, TB>>>(ei);                 // 3
    k_scan1<<<SCAN_CHUNKS, 1024>>>();                               // 4 <- profiled
    k_scan2<<<1, 128>>>();                                          // 5
    k_scan3<<<nblkN, TB>>>(x);                                      // 6
    k_fill<<<(N_EDGES / 2 + TB - 1) / TB, TB>>>(ei);                // 7

    k_agg20<<<nblkW, TB>>>();                                       // 8
    k_mm1<<<mmGrid, TB>>>(W1, b1);                                  // 9
    k_agg64<<<nblkW, TB>>>();                                       // 10
    k_mm2<<<mmGrid, TB>>>(W2, b2);                                  // 11
    k_agg64_pool<<<nblkW, TB>>>(batch);                             // 12
    k_final<<<N_GRAPHS, 128>>>(W3, b3, Wl, bl, out);                // 13
}